// round 8
// baseline (speedup 1.0000x reference)
#include <cuda_runtime.h>
#include <cuda_fp16.h>
#include <float.h>
#include <math.h>
#include <cstdint>

#define N_NODES 131072
#define B_SEG   1024
#define H_DIM   128
#define TILE_N  128
#define NTILES  (N_NODES / TILE_N)
#define NSTAGES 3

// Tiles: [128 rows][136 halves] -> 272 B row stride (16B-aligned, 17x16B units)
#define A_STRIDE 136
#define B_STRIDE 136

__device__ float g_v[N_NODES];

// ---- k_node smem layout (bytes) ----
static constexpr int STAGE   = 34816;                   // Ah per stage
static constexpr int SM_B    = NSTAGES * STAGE;         // 104448
static constexpr int SM_FLT  = SM_B + 34816;            // 139264
// floats: lins[3][128], ps[512], b1s[128], w2s[128] = 1152 floats
static constexpr int SMEM_K1 = SM_FLT + 1152 * 4;       // 143872

// ---------------------------------------------------------------------------
__device__ __forceinline__ uint32_t smem_u32(const void* p) {
    uint32_t a;
    asm("{ .reg .u64 t; cvta.to.shared.u64 t, %1; cvt.u32.u64 %0, t; }"
        : "=r"(a) : "l"(p));
    return a;
}
__device__ __forceinline__ void bar_sync(int id, int cnt) {
    asm volatile("bar.sync %0, %1;" :: "r"(id), "r"(cnt) : "memory");
}
__device__ __forceinline__ void bar_arrive(int id, int cnt) {
    asm volatile("bar.arrive %0, %1;" :: "r"(id), "r"(cnt) : "memory");
}
__device__ __forceinline__ void ldsm_x4(uint32_t* r, uint32_t a) {
    asm volatile("ldmatrix.sync.aligned.m8n8.x4.shared.b16 {%0,%1,%2,%3}, [%4];"
                 : "=r"(r[0]), "=r"(r[1]), "=r"(r[2]), "=r"(r[3]) : "r"(a));
}
__device__ __forceinline__ void ldsm_x2t(uint32_t* r, uint32_t a) {
    asm volatile("ldmatrix.sync.aligned.m8n8.x2.trans.shared.b16 {%0,%1}, [%2];"
                 : "=r"(r[0]), "=r"(r[1]) : "r"(a));
}
__device__ __forceinline__ void mma16816(float* d, const uint32_t* a, const uint32_t* b) {
    asm volatile(
        "mma.sync.aligned.m16n8k16.row.col.f32.f16.f16.f32 "
        "{%0,%1,%2,%3}, {%4,%5,%6,%7}, {%8,%9}, {%0,%1,%2,%3};"
        : "+f"(d[0]), "+f"(d[1]), "+f"(d[2]), "+f"(d[3])
        : "r"(a[0]), "r"(a[1]), "r"(a[2]), "r"(a[3]), "r"(b[0]), "r"(b[1]));
}

// ---------------------------------------------------------------------------
// Kernel 1: persistent warp-specialized node readout (fp16 single-term MMA)
//   producers (warps 0-7): load embedding, fold lin, fp16 A -> 3-stage ring
//   consumers (warps 8-15): mma.sync GEMM + relu+W2 epilogue
// ---------------------------------------------------------------------------
__global__ __launch_bounds__(512, 1)
void k_node(const float4* __restrict__ emb4,
            const float*  __restrict__ W_lins,
            const float*  __restrict__ b_lins,
            const float*  __restrict__ W1,
            const float*  __restrict__ b1,
            const float*  __restrict__ W2,
            const float*  __restrict__ b2)
{
    extern __shared__ __align__(16) char smem[];
    char*  Bh   = smem + SM_B;
    float* lins = (float*)(smem + SM_FLT);   // [3][128]
    float* ps   = lins + NSTAGES * 128;      // [128][4]
    float* b1s  = ps + 512;                  // [128]
    float* w2s  = b1s + 128;                 // [128]

    const int tid  = threadIdx.x;
    const int lane = tid & 31;
    const int wid  = tid >> 5;
    const bool producer = (wid < 8);
    const uint32_t sbase = smem_u32(smem);

    // one-time staging: W1 -> fp16 B tile, b1s, w2s
    for (int i = tid; i < 128 * 128 / 4; i += 512) {
        float4 w = ((const float4*)W1)[i];
        int c  = i >> 5;
        int h4 = (i & 31) * 4;
        int off = (c * B_STRIDE + h4) * 2;
        *(__half2*)(Bh + off)     = __floats2half2_rn(w.x, w.y);
        *(__half2*)(Bh + off + 4) = __floats2half2_rn(w.z, w.w);
    }
    if (tid < 128) { b1s[tid] = b1[tid]; w2s[tid] = W2[tid]; }

    float wlr[3][4];
    if (producer) {
        #pragma unroll
        for (int r = 0; r < 3; ++r)
            #pragma unroll
            for (int cc = 0; cc < 4; ++cc)
                wlr[r][cc] = W_lins[r * 128 + cc * 32 + lane];
    }
    const float cst = b_lins[0] + b_lins[1] + b_lins[2] + b2[0];
    __syncthreads();

    int it = 0;
    for (int t = blockIdx.x; t < NTILES; t += gridDim.x, ++it) {
        const int s  = it % NSTAGES;
        const int n0 = t * TILE_N;

        if (producer) {
            if (it >= NSTAGES) bar_sync(5 + s, 512);     // wait stage empty
            char* AhS = smem + s * STAGE;

            #pragma unroll
            for (int ii = 0; ii < 16; ii += 4) {
                int nl = wid * 16 + ii;
                float4 x[4][4];
                #pragma unroll
                for (int nn = 0; nn < 4; ++nn)
                    #pragma unroll
                    for (int cc = 0; cc < 4; ++cc)
                        x[nn][cc] = emb4[(size_t)(n0 + nl + nn) * 128 + cc * 32 + lane];

                #pragma unroll
                for (int nn = 0; nn < 4; ++nn) {
                    float l = 0.f;
                    #pragma unroll
                    for (int cc = 0; cc < 4; ++cc) {
                        int c = cc * 32 + lane;
                        l = fmaf(x[nn][cc].x, wlr[0][cc], l);
                        l = fmaf(x[nn][cc].y, wlr[1][cc], l);
                        l = fmaf(x[nn][cc].z, wlr[2][cc], l);
                        *(__half*)(AhS + ((nl + nn) * A_STRIDE + c) * 2) =
                            __float2half_rn(x[nn][cc].w);
                    }
                    #pragma unroll
                    for (int d = 16; d > 0; d >>= 1)
                        l += __shfl_xor_sync(0xffffffffu, l, d);
                    if (lane == 0) lins[s * 128 + nl + nn] = l;
                }
            }
            __threadfence_block();
            bar_arrive(2 + s, 512);                      // signal stage full
        } else {
            bar_sync(2 + s, 512);                        // wait stage full

            const int cw = wid - 8;
            const int wm = (cw >> 2) * 64;
            const int wn = (cw & 3) * 32;
            const int lr = lane & 15;
            const int lk = (lane >> 4) * 8;

            float acc[4][4][4];
            #pragma unroll
            for (int mt = 0; mt < 4; ++mt)
                #pragma unroll
                for (int nt = 0; nt < 4; ++nt)
                    #pragma unroll
                    for (int r = 0; r < 4; ++r) acc[mt][nt][r] = 0.f;

            const uint32_t aAh = sbase + s * STAGE;
            const uint32_t aBh = sbase + SM_B;

            #pragma unroll
            for (int k0 = 0; k0 < 128; k0 += 16) {
                uint32_t bh[4][2];
                #pragma unroll
                for (int nt = 0; nt < 4; ++nt) {
                    uint32_t boff = (uint32_t)(((k0 + lr) * B_STRIDE + wn + nt * 8) * 2);
                    ldsm_x2t(bh[nt], aBh + boff);
                }
                #pragma unroll
                for (int mt = 0; mt < 4; ++mt) {
                    uint32_t aoff = (uint32_t)(((wm + mt * 16 + lr) * A_STRIDE + k0 + lk) * 2);
                    uint32_t ah[4];
                    ldsm_x4(ah, aAh + aoff);
                    #pragma unroll
                    for (int nt = 0; nt < 4; ++nt)
                        mma16816(acc[mt][nt], ah, bh[nt]);
                }
            }

            // epilogue: relu + W2 contraction inside fragments
            const int gid = lane >> 2;
            const int tig = lane & 3;
            float rp[4][2];
            #pragma unroll
            for (int mt = 0; mt < 4; ++mt) { rp[mt][0] = 0.f; rp[mt][1] = 0.f; }

            #pragma unroll
            for (int mt = 0; mt < 4; ++mt)
                #pragma unroll
                for (int nt = 0; nt < 4; ++nt)
                    #pragma unroll
                    for (int r = 0; r < 4; ++r) {
                        int col = wn + nt * 8 + tig * 2 + (r & 1);
                        float hv = acc[mt][nt][r] + b1s[col];
                        rp[mt][r >> 1] = fmaf(fmaxf(hv, 0.f), w2s[col], rp[mt][r >> 1]);
                    }

            #pragma unroll
            for (int mt = 0; mt < 4; ++mt)
                #pragma unroll
                for (int h = 0; h < 2; ++h) {
                    float sum = rp[mt][h];
                    sum += __shfl_xor_sync(0xffffffffu, sum, 1);
                    sum += __shfl_xor_sync(0xffffffffu, sum, 2);
                    if (tig == 0)
                        ps[(wm + mt * 16 + gid + h * 8) * 4 + (cw & 3)] = sum;
                }
            bar_sync(8, 256);                            // consumers only

            int ctid = tid - 256;
            if (ctid < 128) {
                g_v[n0 + ctid] = lins[s * 128 + ctid] + ps[ctid * 4] + ps[ctid * 4 + 1]
                               + ps[ctid * 4 + 2] + ps[ctid * 4 + 3] + cst;
            }
            bar_arrive(5 + s, 512);                      // signal stage empty
        }
    }
}

// ---------------------------------------------------------------------------
// Kernel 2: warp-per-segment aggregation; warp-cooperative 32-ary lower_bound
// ---------------------------------------------------------------------------
#define CAP 1024

__device__ __forceinline__ int wlb32(const int* __restrict__ a, int n, int key, int lane)
{
    int lo = 0, hi = n;                       // answer in [lo, hi]
    while (hi - lo > 32) {
        int width = hi - lo;
        int idx = lo + (int)(((long)(lane + 1) * width) >> 5);
        bool pred = (lane < 31) && (a[idx] < key);
        int c = __popc(__ballot_sync(0xffffffffu, pred));
        hi = lo + (int)(((long)(c + 1) * width) >> 5);
        lo = lo + (int)(((long)c * width) >> 5);
    }
    int idx = lo + lane;
    bool pred = (idx < hi) && (a[idx] < key);
    return lo + __popc(__ballot_sync(0xffffffffu, pred));
}

__global__ __launch_bounds__(128)
void k_agg(const int*   __restrict__ batch,
           const float* __restrict__ Wm1,
           const float* __restrict__ bm1,
           const float* __restrict__ Wm2,
           const float* __restrict__ bm2,
           float* __restrict__ out)
{
    __shared__ float ssort[4][256];
    __shared__ float sv[CAP];
    __shared__ float red[128];
    __shared__ float aggd[12];
    __shared__ int   dlist[4];
    __shared__ int   dcount;
    __shared__ int   s_se[2];

    const int tid  = threadIdx.x;
    const int lane = tid & 31;
    const int wid  = tid >> 5;
    const int seg  = blockIdx.x * 4 + wid;

    if (tid == 0) dcount = 0;
    __syncthreads();

    const int start = wlb32(batch, N_NODES, seg, lane);
    const int end   = wlb32(batch, N_NODES, seg + 1, lane);
    const int cnt   = end - start;

    if (cnt > 256) {
        if (lane == 0) { int p = atomicAdd(&dcount, 1); dlist[p] = wid; }
    } else {
        float v[8];
        float sum = 0.f;
        #pragma unroll
        for (int r = 0; r < 8; ++r) {
            int i = r * 32 + lane;
            float x = (i < cnt) ? g_v[start + i] : FLT_MAX;
            v[r] = x;
            if (i < cnt) sum += x;
        }
        #pragma unroll
        for (int d = 16; d > 0; d >>= 1) sum += __shfl_xor_sync(0xffffffffu, sum, d);

        // fixed 256-element bitonic network: idx = r*32 + lane
        #pragma unroll
        for (int k = 2; k <= 256; k <<= 1) {
            #pragma unroll
            for (int j = k >> 1; j > 0; j >>= 1) {
                if (j >= 32) {
                    const int jr = j >> 5;
                    #pragma unroll
                    for (int r = 0; r < 8; ++r) {
                        if ((r & jr) == 0) {
                            int rp = r | jr;
                            bool up = (((r * 32) & k) == 0);
                            float a = v[r], b = v[rp];
                            float lo = fminf(a, b), hi = fmaxf(a, b);
                            v[r]  = up ? lo : hi;
                            v[rp] = up ? hi : lo;
                        }
                    }
                } else {
                    #pragma unroll
                    for (int r = 0; r < 8; ++r) {
                        float other = __shfl_xor_sync(0xffffffffu, v[r], j);
                        bool lower = (lane & j) == 0;
                        bool up = (k < 32) ? ((lane & k) == 0) : (((r * 32) & k) == 0);
                        v[r] = (up == lower) ? fminf(v[r], other) : fmaxf(v[r], other);
                    }
                }
            }
        }

        #pragma unroll
        for (int r = 0; r < 8; ++r) ssort[wid][r * 32 + lane] = v[r];
        __syncwarp();

        float agg[12];
        if (cnt > 0) {
            const float* sw = ssort[wid];
            agg[0] = sum / (float)cnt;
            agg[1] = sw[cnt - 1];
            agg[2] = sw[0];
            #pragma unroll
            for (int qi = 0; qi < 9; ++qi) {
                float q    = (float)(qi + 1) * 0.1f;
                float pos  = q * (float)(cnt - 1);
                float f    = floorf(pos);
                float frac = pos - f;
                int lo = (int)f;
                if (lo > cnt - 1) lo = cnt - 1;
                if (lo < 0) lo = 0;
                int hi = lo + 1;
                if (hi > cnt - 1) hi = cnt - 1;
                agg[3 + qi] = sw[lo] + frac * (sw[hi] - sw[lo]);
            }
        } else {
            #pragma unroll
            for (int i = 0; i < 12; ++i) agg[i] = 0.f;
        }

        // MLP in-warp
        float c = 0.f;
        #pragma unroll
        for (int hh = 0; hh < 4; ++hh) {
            int h = hh * 32 + lane;
            float hj = bm1[h];
            #pragma unroll
            for (int i = 0; i < 12; ++i)
                hj = fmaf(agg[i], Wm1[i * H_DIM + h], hj);
            c = fmaf(fmaxf(hj, 0.f), Wm2[h], c);
        }
        #pragma unroll
        for (int d = 16; d > 0; d >>= 1) c += __shfl_xor_sync(0xffffffffu, c, d);
        if (lane == 0) out[seg] = c + bm2[0];
    }
    __syncthreads();

    // ---- deferred (cnt > 256) segments: block-wide bitonic path ----
    for (int d = 0; d < dcount; ++d) {
        const int w = dlist[d];
        const int dseg = blockIdx.x * 4 + w;

        if (tid == 0) {
            // serial bounds fine here (rare path)
            s_se[0] = 0; s_se[1] = 0;
        }
        __syncthreads();
        if (wid == 0) {
            int st = wlb32(batch, N_NODES, dseg, lane);
            int en = wlb32(batch, N_NODES, dseg + 1, lane);
            if (lane == 0) { s_se[0] = st; s_se[1] = en; }
        }
        __syncthreads();
        const int dstart = s_se[0];
        const int dcnt   = s_se[1] - s_se[0];

        int m = 1;
        while (m < dcnt) m <<= 1;
        if (m > CAP) m = CAP;

        for (int i = tid; i < m; i += 128)
            sv[i] = (i < dcnt && i < CAP) ? g_v[dstart + i] : FLT_MAX;
        __syncthreads();

        for (int ksz = 2; ksz <= m; ksz <<= 1) {
            for (int j = ksz >> 1; j > 0; j >>= 1) {
                for (int i = tid; i < m; i += 128) {
                    int p = i ^ j;
                    if (p > i) {
                        bool up = ((i & ksz) == 0);
                        float x = sv[i], y = sv[p];
                        if (up ? (x > y) : (x < y)) { sv[i] = y; sv[p] = x; }
                    }
                }
                __syncthreads();
            }
        }

        float ls = 0.f;
        for (int i = tid; i < dcnt; i += 128) ls += sv[i];
        red[tid] = ls;
        __syncthreads();
        for (int s = 64; s > 0; s >>= 1) {
            if (tid < s) red[tid] += red[tid + s];
            __syncthreads();
        }
        if (tid == 0) aggd[0] = red[0] / (float)dcnt;
        if (tid == 1) aggd[1] = sv[dcnt - 1];
        if (tid == 2) aggd[2] = sv[0];
        if (tid < 9) {
            float q    = (float)(tid + 1) * 0.1f;
            float pos  = q * (float)(dcnt - 1);
            float f    = floorf(pos);
            float frac = pos - f;
            int lo = (int)f;
            if (lo > dcnt - 1) lo = dcnt - 1;
            if (lo < 0) lo = 0;
            int hi = lo + 1;
            if (hi > dcnt - 1) hi = dcnt - 1;
            aggd[3 + tid] = sv[lo] + frac * (sv[hi] - sv[lo]);
        }
        __syncthreads();

        float contrib = 0.f;
        if (tid < H_DIM) {
            float hj = bm1[tid];
            #pragma unroll
            for (int i = 0; i < 12; ++i)
                hj = fmaf(aggd[i], Wm1[i * H_DIM + tid], hj);
            hj = fmaxf(hj, 0.f);
            contrib = hj * Wm2[tid];
        }
        red[tid] = contrib;
        __syncthreads();
        for (int s = 64; s > 0; s >>= 1) {
            if (tid < s) red[tid] += red[tid + s];
            __syncthreads();
        }
        if (tid == 0) out[dseg] = red[0] + bm2[0];
        __syncthreads();
    }
}

// ---------------------------------------------------------------------------
extern "C" void kernel_launch(void* const* d_in, const int* in_sizes, int n_in,
                              void* d_out, int out_size)
{
    const float4* emb4   = (const float4*)d_in[0];
    const int*    batch  = (const int*)  d_in[1];
    const float*  W_lins = (const float*)d_in[2];
    const float*  b_lins = (const float*)d_in[3];
    const float*  W1     = (const float*)d_in[4];
    const float*  b1     = (const float*)d_in[5];
    const float*  W2     = (const float*)d_in[6];
    const float*  b2     = (const float*)d_in[7];
    const float*  Wm1    = (const float*)d_in[8];
    const float*  bm1    = (const float*)d_in[9];
    const float*  Wm2    = (const float*)d_in[10];
    const float*  bm2    = (const float*)d_in[11];
    float* out = (float*)d_out;

    static int nsm = 0;
    if (nsm == 0) {
        cudaDeviceGetAttribute(&nsm, cudaDevAttrMultiProcessorCount, 0);
        if (nsm <= 0) nsm = 148;
        cudaFuncSetAttribute(k_node, cudaFuncAttributeMaxDynamicSharedMemorySize, SMEM_K1);
    }

    k_node<<<nsm, 512, SMEM_K1>>>(emb4, W_lins, b_lins, W1, b1, W2, b2);
    k_agg<<<B_SEG / 4, 128>>>(batch, Wm1, bm1, Wm2, bm2, out);
}

// round 9
// speedup vs baseline: 1.2880x; 1.2880x over previous
#include <cuda_runtime.h>
#include <cuda_fp16.h>
#include <float.h>
#include <math.h>
#include <cstdint>

#define N_NODES 131072
#define B_SEG   1024
#define H_DIM   128
#define TILE_N  128
#define NTILES  (N_NODES / TILE_N)
#define NSTAGES 3

// Tiles: [128 rows][136 halves] -> 272 B row stride (16B-aligned, 17x16B units)
#define A_STRIDE 136
#define B_STRIDE 136

__device__ float g_v[N_NODES];
__device__ int   g_off[B_SEG + 1];

// ---- k_node smem layout (bytes) ----
static constexpr int STAGE   = 34816;                   // Ah per stage
static constexpr int SM_B    = NSTAGES * STAGE;         // 104448
static constexpr int SM_FLT  = SM_B + 34816;            // 139264
// floats: lins[3][128], ps[512], b1s[128], w2s[128] = 1152 floats
static constexpr int SMEM_K1 = SM_FLT + 1152 * 4;       // 143872

// ---------------------------------------------------------------------------
__device__ __forceinline__ uint32_t smem_u32(const void* p) {
    uint32_t a;
    asm("{ .reg .u64 t; cvta.to.shared.u64 t, %1; cvt.u32.u64 %0, t; }"
        : "=r"(a) : "l"(p));
    return a;
}
__device__ __forceinline__ void bar_sync(int id, int cnt) {
    asm volatile("bar.sync %0, %1;" :: "r"(id), "r"(cnt) : "memory");
}
__device__ __forceinline__ void bar_arrive(int id, int cnt) {
    asm volatile("bar.arrive %0, %1;" :: "r"(id), "r"(cnt) : "memory");
}
__device__ __forceinline__ void ldsm_x4(uint32_t* r, uint32_t a) {
    asm volatile("ldmatrix.sync.aligned.m8n8.x4.shared.b16 {%0,%1,%2,%3}, [%4];"
                 : "=r"(r[0]), "=r"(r[1]), "=r"(r[2]), "=r"(r[3]) : "r"(a));
}
__device__ __forceinline__ void ldsm_x2t(uint32_t* r, uint32_t a) {
    asm volatile("ldmatrix.sync.aligned.m8n8.x2.trans.shared.b16 {%0,%1}, [%2];"
                 : "=r"(r[0]), "=r"(r[1]) : "r"(a));
}
__device__ __forceinline__ void mma16816(float* d, const uint32_t* a, const uint32_t* b) {
    asm volatile(
        "mma.sync.aligned.m16n8k16.row.col.f32.f16.f16.f32 "
        "{%0,%1,%2,%3}, {%4,%5,%6,%7}, {%8,%9}, {%0,%1,%2,%3};"
        : "+f"(d[0]), "+f"(d[1]), "+f"(d[2]), "+f"(d[3])
        : "r"(a[0]), "r"(a[1]), "r"(a[2]), "r"(a[3]), "r"(b[0]), "r"(b[1]));
}

// ---------------------------------------------------------------------------
// Kernel 1: persistent warp-specialized node readout (fp16 single-term MMA)
//   prelude:  all threads scatter segment offsets (batch is sorted)
//   producers (warps 0-7): load embedding, fold lin, fp16 A -> 3-stage ring
//   consumers (warps 8-15): mma.sync GEMM + relu+W2 epilogue
// ---------------------------------------------------------------------------
__global__ __launch_bounds__(512, 1)
void k_node(const float4* __restrict__ emb4,
            const int*    __restrict__ batch,
            const float*  __restrict__ W_lins,
            const float*  __restrict__ b_lins,
            const float*  __restrict__ W1,
            const float*  __restrict__ b1,
            const float*  __restrict__ W2,
            const float*  __restrict__ b2)
{
    extern __shared__ __align__(16) char smem[];
    char*  Bh   = smem + SM_B;
    float* lins = (float*)(smem + SM_FLT);   // [3][128]
    float* ps   = lins + NSTAGES * 128;      // [128][4]
    float* b1s  = ps + 512;                  // [128]
    float* w2s  = b1s + 128;                 // [128]

    const int tid  = threadIdx.x;
    const int lane = tid & 31;
    const int wid  = tid >> 5;
    const bool producer = (wid < 8);
    const uint32_t sbase = smem_u32(smem);

    // ---- prelude: segment-offset scatter (batch sorted) ----
    for (int i = blockIdx.x * 512 + tid; i < N_NODES; i += gridDim.x * 512) {
        int b    = batch[i];
        int prev = (i == 0) ? -1 : batch[i - 1];
        for (int bb = prev + 1; bb <= b; ++bb) g_off[bb] = i;
        if (i == N_NODES - 1)
            for (int bb = b + 1; bb <= B_SEG; ++bb) g_off[bb] = N_NODES;
    }

    // one-time staging: W1 -> fp16 B tile, b1s, w2s
    for (int i = tid; i < 128 * 128 / 4; i += 512) {
        float4 w = ((const float4*)W1)[i];
        int c  = i >> 5;
        int h4 = (i & 31) * 4;
        int off = (c * B_STRIDE + h4) * 2;
        *(__half2*)(Bh + off)     = __floats2half2_rn(w.x, w.y);
        *(__half2*)(Bh + off + 4) = __floats2half2_rn(w.z, w.w);
    }
    if (tid < 128) { b1s[tid] = b1[tid]; w2s[tid] = W2[tid]; }

    float wlr[3][4];
    if (producer) {
        #pragma unroll
        for (int r = 0; r < 3; ++r)
            #pragma unroll
            for (int cc = 0; cc < 4; ++cc)
                wlr[r][cc] = W_lins[r * 128 + cc * 32 + lane];
    }
    const float cst = b_lins[0] + b_lins[1] + b_lins[2] + b2[0];
    __syncthreads();

    int it = 0;
    for (int t = blockIdx.x; t < NTILES; t += gridDim.x, ++it) {
        const int s  = it % NSTAGES;
        const int n0 = t * TILE_N;

        if (producer) {
            if (it >= NSTAGES) bar_sync(5 + s, 512);     // wait stage empty
            char* AhS = smem + s * STAGE;

            #pragma unroll 1
            for (int ii = 0; ii < 16; ii += 4) {
                int nl = wid * 16 + ii;
                float4 x[4][4];
                #pragma unroll
                for (int nn = 0; nn < 4; ++nn)
                    #pragma unroll
                    for (int cc = 0; cc < 4; ++cc)
                        x[nn][cc] = emb4[(size_t)(n0 + nl + nn) * 128 + cc * 32 + lane];

                #pragma unroll
                for (int nn = 0; nn < 4; ++nn) {
                    float l = 0.f;
                    #pragma unroll
                    for (int cc = 0; cc < 4; ++cc) {
                        int c = cc * 32 + lane;
                        l = fmaf(x[nn][cc].x, wlr[0][cc], l);
                        l = fmaf(x[nn][cc].y, wlr[1][cc], l);
                        l = fmaf(x[nn][cc].z, wlr[2][cc], l);
                        *(__half*)(AhS + ((nl + nn) * A_STRIDE + c) * 2) =
                            __float2half_rn(x[nn][cc].w);
                    }
                    #pragma unroll
                    for (int d = 16; d > 0; d >>= 1)
                        l += __shfl_xor_sync(0xffffffffu, l, d);
                    if (lane == 0) lins[s * 128 + nl + nn] = l;
                }
            }
            __threadfence_block();
            bar_arrive(2 + s, 512);                      // signal stage full
        } else {
            bar_sync(2 + s, 512);                        // wait stage full

            const int cw = wid - 8;
            const int wm = (cw >> 2) * 64;
            const int wn = (cw & 3) * 32;
            const int lr = lane & 15;
            const int lk = (lane >> 4) * 8;

            float acc[4][4][4];
            #pragma unroll
            for (int mt = 0; mt < 4; ++mt)
                #pragma unroll
                for (int nt = 0; nt < 4; ++nt)
                    #pragma unroll
                    for (int r = 0; r < 4; ++r) acc[mt][nt][r] = 0.f;

            const uint32_t aAh = sbase + s * STAGE;
            const uint32_t aBh = sbase + SM_B;

            #pragma unroll
            for (int k0 = 0; k0 < 128; k0 += 16) {
                uint32_t bh[4][2];
                #pragma unroll
                for (int nt = 0; nt < 4; ++nt) {
                    uint32_t boff = (uint32_t)(((k0 + lr) * B_STRIDE + wn + nt * 8) * 2);
                    ldsm_x2t(bh[nt], aBh + boff);
                }
                #pragma unroll
                for (int mt = 0; mt < 4; ++mt) {
                    uint32_t aoff = (uint32_t)(((wm + mt * 16 + lr) * A_STRIDE + k0 + lk) * 2);
                    uint32_t ah[4];
                    ldsm_x4(ah, aAh + aoff);
                    #pragma unroll
                    for (int nt = 0; nt < 4; ++nt)
                        mma16816(acc[mt][nt], ah, bh[nt]);
                }
            }

            // epilogue: relu + W2 contraction inside fragments
            const int gid = lane >> 2;
            const int tig = lane & 3;
            float rp[4][2];
            #pragma unroll
            for (int mt = 0; mt < 4; ++mt) { rp[mt][0] = 0.f; rp[mt][1] = 0.f; }

            #pragma unroll
            for (int mt = 0; mt < 4; ++mt)
                #pragma unroll
                for (int nt = 0; nt < 4; ++nt)
                    #pragma unroll
                    for (int r = 0; r < 4; ++r) {
                        int col = wn + nt * 8 + tig * 2 + (r & 1);
                        float hv = acc[mt][nt][r] + b1s[col];
                        rp[mt][r >> 1] = fmaf(fmaxf(hv, 0.f), w2s[col], rp[mt][r >> 1]);
                    }

            #pragma unroll
            for (int mt = 0; mt < 4; ++mt)
                #pragma unroll
                for (int h = 0; h < 2; ++h) {
                    float sum = rp[mt][h];
                    sum += __shfl_xor_sync(0xffffffffu, sum, 1);
                    sum += __shfl_xor_sync(0xffffffffu, sum, 2);
                    if (tig == 0)
                        ps[(wm + mt * 16 + gid + h * 8) * 4 + (cw & 3)] = sum;
                }
            bar_sync(8, 256);                            // consumers only

            int ctid = tid - 256;
            if (ctid < 128) {
                g_v[n0 + ctid] = lins[s * 128 + ctid] + ps[ctid * 4] + ps[ctid * 4 + 1]
                               + ps[ctid * 4 + 2] + ps[ctid * 4 + 3] + cst;
            }
            bar_arrive(5 + s, 512);                      // signal stage empty
        }
    }
}

// ---------------------------------------------------------------------------
// Kernel 2: warp-per-segment aggregation; offsets precomputed in k_node
// ---------------------------------------------------------------------------
#define CAP 1024

__global__ __launch_bounds__(128)
void k_agg(const float* __restrict__ Wm1,
           const float* __restrict__ bm1,
           const float* __restrict__ Wm2,
           const float* __restrict__ bm2,
           float* __restrict__ out)
{
    __shared__ float ssort[4][256];
    __shared__ float sv[CAP];
    __shared__ float red[128];
    __shared__ float aggd[12];
    __shared__ int   dlist[4];
    __shared__ int   dcount;

    const int tid  = threadIdx.x;
    const int lane = tid & 31;
    const int wid  = tid >> 5;
    const int seg  = blockIdx.x * 4 + wid;

    if (tid == 0) dcount = 0;
    __syncthreads();

    const int start = g_off[seg];
    const int cnt   = g_off[seg + 1] - start;

    if (cnt > 256) {
        if (lane == 0) { int p = atomicAdd(&dcount, 1); dlist[p] = wid; }
    } else {
        float v[8];
        float sum = 0.f;
        #pragma unroll
        for (int r = 0; r < 8; ++r) {
            int i = r * 32 + lane;
            float x = (i < cnt) ? g_v[start + i] : FLT_MAX;
            v[r] = x;
            if (i < cnt) sum += x;
        }
        #pragma unroll
        for (int d = 16; d > 0; d >>= 1) sum += __shfl_xor_sync(0xffffffffu, sum, d);

        // fixed 256-element bitonic network: idx = r*32 + lane
        #pragma unroll
        for (int k = 2; k <= 256; k <<= 1) {
            #pragma unroll
            for (int j = k >> 1; j > 0; j >>= 1) {
                if (j >= 32) {
                    const int jr = j >> 5;
                    #pragma unroll
                    for (int r = 0; r < 8; ++r) {
                        if ((r & jr) == 0) {
                            int rp = r | jr;
                            bool up = (((r * 32) & k) == 0);
                            float a = v[r], b = v[rp];
                            float lo = fminf(a, b), hi = fmaxf(a, b);
                            v[r]  = up ? lo : hi;
                            v[rp] = up ? hi : lo;
                        }
                    }
                } else {
                    #pragma unroll
                    for (int r = 0; r < 8; ++r) {
                        float other = __shfl_xor_sync(0xffffffffu, v[r], j);
                        bool lower = (lane & j) == 0;
                        bool up = (k < 32) ? ((lane & k) == 0) : (((r * 32) & k) == 0);
                        v[r] = (up == lower) ? fminf(v[r], other) : fmaxf(v[r], other);
                    }
                }
            }
        }

        #pragma unroll
        for (int r = 0; r < 8; ++r) ssort[wid][r * 32 + lane] = v[r];
        __syncwarp();

        float agg[12];
        if (cnt > 0) {
            const float* sw = ssort[wid];
            agg[0] = sum / (float)cnt;
            agg[1] = sw[cnt - 1];
            agg[2] = sw[0];
            #pragma unroll
            for (int qi = 0; qi < 9; ++qi) {
                float q    = (float)(qi + 1) * 0.1f;
                float pos  = q * (float)(cnt - 1);
                float f    = floorf(pos);
                float frac = pos - f;
                int lo = (int)f;
                if (lo > cnt - 1) lo = cnt - 1;
                if (lo < 0) lo = 0;
                int hi = lo + 1;
                if (hi > cnt - 1) hi = cnt - 1;
                agg[3 + qi] = sw[lo] + frac * (sw[hi] - sw[lo]);
            }
        } else {
            #pragma unroll
            for (int i = 0; i < 12; ++i) agg[i] = 0.f;
        }

        // MLP in-warp
        float c = 0.f;
        #pragma unroll
        for (int hh = 0; hh < 4; ++hh) {
            int h = hh * 32 + lane;
            float hj = bm1[h];
            #pragma unroll
            for (int i = 0; i < 12; ++i)
                hj = fmaf(agg[i], Wm1[i * H_DIM + h], hj);
            c = fmaf(fmaxf(hj, 0.f), Wm2[h], c);
        }
        #pragma unroll
        for (int d = 16; d > 0; d >>= 1) c += __shfl_xor_sync(0xffffffffu, c, d);
        if (lane == 0) out[seg] = c + bm2[0];
    }
    __syncthreads();

    // ---- deferred (cnt > 256) segments: block-wide bitonic path ----
    for (int d = 0; d < dcount; ++d) {
        const int dseg   = blockIdx.x * 4 + dlist[d];
        const int dstart = g_off[dseg];
        const int dcnt   = g_off[dseg + 1] - dstart;

        int m = 1;
        while (m < dcnt) m <<= 1;
        if (m > CAP) m = CAP;

        for (int i = tid; i < m; i += 128)
            sv[i] = (i < dcnt && i < CAP) ? g_v[dstart + i] : FLT_MAX;
        __syncthreads();

        for (int ksz = 2; ksz <= m; ksz <<= 1) {
            for (int j = ksz >> 1; j > 0; j >>= 1) {
                for (int i = tid; i < m; i += 128) {
                    int p = i ^ j;
                    if (p > i) {
                        bool up = ((i & ksz) == 0);
                        float x = sv[i], y = sv[p];
                        if (up ? (x > y) : (x < y)) { sv[i] = y; sv[p] = x; }
                    }
                }
                __syncthreads();
            }
        }

        float ls = 0.f;
        for (int i = tid; i < dcnt; i += 128) ls += sv[i];
        red[tid] = ls;
        __syncthreads();
        for (int s = 64; s > 0; s >>= 1) {
            if (tid < s) red[tid] += red[tid + s];
            __syncthreads();
        }
        if (tid == 0) aggd[0] = red[0] / (float)dcnt;
        if (tid == 1) aggd[1] = sv[dcnt - 1];
        if (tid == 2) aggd[2] = sv[0];
        if (tid < 9) {
            float q    = (float)(tid + 1) * 0.1f;
            float pos  = q * (float)(dcnt - 1);
            float f    = floorf(pos);
            float frac = pos - f;
            int lo = (int)f;
            if (lo > dcnt - 1) lo = dcnt - 1;
            if (lo < 0) lo = 0;
            int hi = lo + 1;
            if (hi > dcnt - 1) hi = dcnt - 1;
            aggd[3 + tid] = sv[lo] + frac * (sv[hi] - sv[lo]);
        }
        __syncthreads();

        float contrib = 0.f;
        if (tid < H_DIM) {
            float hj = bm1[tid];
            #pragma unroll
            for (int i = 0; i < 12; ++i)
                hj = fmaf(aggd[i], Wm1[i * H_DIM + tid], hj);
            hj = fmaxf(hj, 0.f);
            contrib = hj * Wm2[tid];
        }
        red[tid] = contrib;
        __syncthreads();
        for (int s = 64; s > 0; s >>= 1) {
            if (tid < s) red[tid] += red[tid + s];
            __syncthreads();
        }
        if (tid == 0) out[dseg] = red[0] + bm2[0];
        __syncthreads();
    }
}

// ---------------------------------------------------------------------------
extern "C" void kernel_launch(void* const* d_in, const int* in_sizes, int n_in,
                              void* d_out, int out_size)
{
    const float4* emb4   = (const float4*)d_in[0];
    const int*    batch  = (const int*)  d_in[1];
    const float*  W_lins = (const float*)d_in[2];
    const float*  b_lins = (const float*)d_in[3];
    const float*  W1     = (const float*)d_in[4];
    const float*  b1     = (const float*)d_in[5];
    const float*  W2     = (const float*)d_in[6];
    const float*  b2     = (const float*)d_in[7];
    const float*  Wm1    = (const float*)d_in[8];
    const float*  bm1    = (const float*)d_in[9];
    const float*  Wm2    = (const float*)d_in[10];
    const float*  bm2    = (const float*)d_in[11];
    float* out = (float*)d_out;

    static int nsm = 0;
    if (nsm == 0) {
        cudaDeviceGetAttribute(&nsm, cudaDevAttrMultiProcessorCount, 0);
        if (nsm <= 0) nsm = 148;
        cudaFuncSetAttribute(k_node, cudaFuncAttributeMaxDynamicSharedMemorySize, SMEM_K1);
    }

    k_node<<<nsm, 512, SMEM_K1>>>(emb4, batch, W_lins, b_lins, W1, b1, W2, b2);
    k_agg<<<B_SEG / 4, 128>>>(Wm1, bm1, Wm2, bm2, out);
}